// round 5
// baseline (speedup 1.0000x reference)
#include <cuda_runtime.h>
#include <math.h>

#define NN 8192
#define CC 512
#define KK 64
#define NBLK (NN/64)        // 128 row-blocks of 64

typedef unsigned long long ull;

// Scratch (device globals — no allocation allowed)
__device__ float g_phi_i[NN*KK];
__device__ float g_phi_j[NN*KK];
__device__ float g_At[CC*KK];   // [c][k] = 1/s^2
__device__ float g_Bt[CC*KK];   // [c][k] = -2*m/s^2
__device__ float g_t3[KK];      // sum_c m^2/s^2
__device__ int   g_nz[2][NBLK]; // per-64-row-block nonzero flags

#define FMA2(d,a,b,c) asm("fma.rn.f32x2 %0, %1, %2, %3;" : "=l"(d) : "l"(a), "l"(b), "l"(c))

__device__ __forceinline__ ull pack2(float lo, float hi) {
    ull r; asm("mov.b64 %0, {%1, %2};" : "=l"(r) : "f"(lo), "f"(hi)); return r;
}
__device__ __forceinline__ void unpack2(ull v, float& lo, float& hi) {
    asm("mov.b64 {%0, %1}, %2;" : "=f"(lo), "=f"(hi) : "l"(v));
}

// ---------------------------------------------------------------------------
// Prep: A = 1/s^2, B = -2*m/s^2 (transposed to [c][k]), t3[k] = sum_c m^2/s^2
// ---------------------------------------------------------------------------
__global__ __launch_bounds__(512)
void prep_kernel(const float* __restrict__ means,
                 const float* __restrict__ scales) {
    const int k = blockIdx.x;
    const int t = threadIdx.x;
    float s   = scales[k*CC + t];
    float m   = means [k*CC + t];
    float is2 = 1.0f / (s * s);
    g_At[t*KK + k] = is2;
    g_Bt[t*KK + k] = -2.0f * m * is2;
    float v = m * m * is2;
    #pragma unroll
    for (int o = 16; o > 0; o >>= 1)
        v += __shfl_down_sync(0xffffffffu, v, o);
    __shared__ float red[16];
    if ((t & 31) == 0) red[t >> 5] = v;
    __syncthreads();
    if (t < 16) {
        float x = red[t];
        #pragma unroll
        for (int o = 8; o > 0; o >>= 1)
            x += __shfl_down_sync(0xffffu, x, o);
        if (t == 0) g_t3[k] = x;
    }
}

// ---------------------------------------------------------------------------
// Phi: f32x2 FMAs, software-pipelined double buffer.
// Block = 64 rows x 64 k, 256 threads, per-thread 4n x 4k (2 packed k-pairs).
//   dist[n,k] = -( sum_c f*(f*A[c,k] + B[c,k]) + t3[k] );  phi = exp(dist)(*w)
// Pipeline: LDG next chunk -> regs, compute current from smem, STS, 1 sync.
// ---------------------------------------------------------------------------
__global__ __launch_bounds__(256)
void phi_kernel(const float* __restrict__ f_i, const float* __restrict__ f_j,
                const float* __restrict__ weights) {
    const int isI = (blockIdx.y == 0);
    const float* __restrict__ f = isI ? f_i : f_j;
    float* __restrict__ phi = isI ? g_phi_i : g_phi_j;
    const int n0 = blockIdx.x * 64;

    __shared__ float fs[2][16][68];   // [buf][c_local][n_local]
    __shared__ float As[2][16][68];   // [buf][c_local][k]
    __shared__ float Bs[2][16][68];

    const int t  = threadIdx.x;
    const int kx = (t & 15) * 4;      // 4 k per thread (2 packed pairs)
    const int ny = (t >> 4) * 4;      // 4 n per thread

    // loader indices (fixed per thread)
    const int lrow = t >> 2;          // f: 64 rows, 4 float4 per row
    const int lc4  = (t & 3) * 4;
    const int lc   = t >> 4;          // A/B: 16 c, 16 float4 per c
    const int lk4  = (t & 15) * 4;

    ull acc[4][2];
    #pragma unroll
    for (int i = 0; i < 4; i++) { acc[i][0] = 0ull; acc[i][1] = 0ull; }

    float4 xf, xa, xb;
    // prologue: load chunk 0
    xf = *(const float4*)(f + (size_t)(n0 + lrow) * CC + lc4);
    xa = *(const float4*)(g_At + (size_t)lc * KK + lk4);
    xb = *(const float4*)(g_Bt + (size_t)lc * KK + lk4);
    {
        fs[0][lc4+0][lrow] = xf.x; fs[0][lc4+1][lrow] = xf.y;
        fs[0][lc4+2][lrow] = xf.z; fs[0][lc4+3][lrow] = xf.w;
        *(float4*)&As[0][lc][lk4] = xa;
        *(float4*)&Bs[0][lc][lk4] = xb;
    }
    __syncthreads();

    #pragma unroll 1
    for (int it = 0; it < 32; it++) {
        const int buf = it & 1;
        const bool more = (it + 1 < 32);
        if (more) {
            int cc = (it + 1) * 16;
            xf = *(const float4*)(f + (size_t)(n0 + lrow) * CC + cc + lc4);
            xa = *(const float4*)(g_At + (size_t)(cc + lc) * KK + lk4);
            xb = *(const float4*)(g_Bt + (size_t)(cc + lc) * KK + lk4);
        }

        #pragma unroll
        for (int c = 0; c < 16; c++) {
            ulonglong2 ap = *(const ulonglong2*)&As[buf][c][kx];
            ulonglong2 bp = *(const ulonglong2*)&Bs[buf][c][kx];
            float4 fv4 = *(const float4*)&fs[buf][c][ny];
            float fv[4] = {fv4.x, fv4.y, fv4.z, fv4.w};
            #pragma unroll
            for (int n = 0; n < 4; n++) {
                ull fd = pack2(fv[n], fv[n]);
                ull t0, t1;
                FMA2(t0, fd, ap.x, bp.x);
                FMA2(acc[n][0], fd, t0, acc[n][0]);
                FMA2(t1, fd, ap.y, bp.y);
                FMA2(acc[n][1], fd, t1, acc[n][1]);
            }
        }

        if (more) {
            const int nb = buf ^ 1;
            fs[nb][lc4+0][lrow] = xf.x; fs[nb][lc4+1][lrow] = xf.y;
            fs[nb][lc4+2][lrow] = xf.z; fs[nb][lc4+3][lrow] = xf.w;
            *(float4*)&As[nb][lc][lk4] = xa;
            *(float4*)&Bs[nb][lc][lk4] = xb;
        }
        __syncthreads();
    }

    // epilogue: d = -(acc + t3);  phi = exp(d) (* w for i-side)
    ull nt3[2];
    nt3[0] = pack2(-g_t3[kx],     -g_t3[kx + 1]);
    nt3[1] = pack2(-g_t3[kx + 2], -g_t3[kx + 3]);
    const ull m1 = pack2(-1.0f, -1.0f);

    float wv[4];
    #pragma unroll
    for (int j = 0; j < 4; j++)
        wv[j] = isI ? weights[kx + j] : 1.0f;

    int lnz = 0;
    #pragma unroll
    for (int n = 0; n < 4; n++) {
        float p[4];
        #pragma unroll
        for (int kp = 0; kp < 2; kp++) {
            ull d;
            FMA2(d, acc[n][kp], m1, nt3[kp]);
            float d0, d1; unpack2(d, d0, d1);
            p[2*kp]   = expf(d0) * wv[2*kp];
            p[2*kp+1] = expf(d1) * wv[2*kp+1];
            lnz |= (p[2*kp] != 0.0f) | (p[2*kp+1] != 0.0f);
        }
        *(float4*)(phi + (size_t)(n0 + ny + n) * KK + kx) =
            make_float4(p[0], p[1], p[2], p[3]);
    }
    int any = __syncthreads_or(lnz);
    if (t == 0) g_nz[isI ? 0 : 1][blockIdx.x] = any;
}

// ---------------------------------------------------------------------------
// GEMM: zero tiles already zeroed by the memset -> exit immediately.
// Nonzero tiles: 64x64, 256 threads, 4x4 micro-tile (proven path).
// ---------------------------------------------------------------------------
__global__ __launch_bounds__(256)
void gemm_kernel(float* __restrict__ out) {
    const int bm = blockIdx.y;
    const int bn = blockIdx.x;

    if (g_nz[0][bm] == 0 || g_nz[1][bn] == 0) return;

    const int t  = threadIdx.x;
    const int txm = (t & 15) * 4;
    const int tyn = (t >> 4) * 4;

    __shared__ float As[64][68];
    __shared__ float Bs[64][68];
    #pragma unroll
    for (int v = 0; v < 4; v++) {
        int vid = t + v * 256;
        int row = vid >> 4;
        int k4  = (vid & 15) * 4;
        float4 a = *(const float4*)(g_phi_i + (size_t)(bm * 64 + row) * KK + k4);
        As[k4+0][row] = a.x; As[k4+1][row] = a.y; As[k4+2][row] = a.z; As[k4+3][row] = a.w;
        float4 b = *(const float4*)(g_phi_j + (size_t)(bn * 64 + row) * KK + k4);
        Bs[k4+0][row] = b.x; Bs[k4+1][row] = b.y; Bs[k4+2][row] = b.z; Bs[k4+3][row] = b.w;
    }
    __syncthreads();

    float acc[4][4];
    #pragma unroll
    for (int i = 0; i < 4; i++)
        #pragma unroll
        for (int j = 0; j < 4; j++) acc[i][j] = 0.f;

    #pragma unroll 8
    for (int k = 0; k < 64; k++) {
        float4 a4 = *(const float4*)&As[k][tyn];
        float4 b4 = *(const float4*)&Bs[k][txm];
        float av[4] = {a4.x, a4.y, a4.z, a4.w};
        float bv[4] = {b4.x, b4.y, b4.z, b4.w};
        #pragma unroll
        for (int i = 0; i < 4; i++)
            #pragma unroll
            for (int j = 0; j < 4; j++)
                acc[i][j] = fmaf(av[i], bv[j], acc[i][j]);
    }

    #pragma unroll
    for (int i = 0; i < 4; i++) {
        size_t row = (size_t)(bm * 64 + tyn + i);
        *(float4*)(out + row * NN + bn * 64 + txm) =
            make_float4(acc[i][0], acc[i][1], acc[i][2], acc[i][3]);
    }
}

// ---------------------------------------------------------------------------
extern "C" void kernel_launch(void* const* d_in, const int* in_sizes, int n_in,
                              void* d_out, int out_size) {
    const float* f_i     = (const float*)d_in[0];
    const float* f_j     = (const float*)d_in[1];
    const float* means   = (const float*)d_in[2];
    const float* scales  = (const float*)d_in[3];
    const float* weights = (const float*)d_in[4];
    float* out = (float*)d_out;

    // Zero the whole output via an async memset node (capture-legal, like
    // cudaMemcpyAsync D2D). gemm then only writes nonzero tiles.
    cudaMemsetAsync(out, 0, (size_t)out_size * sizeof(float));

    prep_kernel<<<KK, 512>>>(means, scales);
    phi_kernel<<<dim3(NBLK, 2), 256>>>(f_i, f_j, weights);
    gemm_kernel<<<dim3(NBLK, NBLK), 256>>>(out);
}

// round 6
// speedup vs baseline: 1.0089x; 1.0089x over previous
#include <cuda_runtime.h>
#include <math.h>

#define NN 8192
#define CC 512
#define KK 64
#define NBLK (NN/64)        // 128 row-blocks of 64 (gemm + flags)
#define PHI_ROWS 128
#define PHI_NBLK (NN/PHI_ROWS)

typedef unsigned long long ull;

// Scratch (device globals — no allocation allowed)
__device__ float g_phi_i[NN*KK];
__device__ float g_phi_j[NN*KK];
__device__ float g_At[CC*KK];   // [c][k] = 1/s^2
__device__ float g_Bt[CC*KK];   // [c][k] = -2*m/s^2
__device__ float g_t3[KK];      // sum_c m^2/s^2
__device__ int   g_nz[2][NBLK]; // per-64-row-block nonzero flags

#define FMA2(d,a,b,c) asm("fma.rn.f32x2 %0, %1, %2, %3;" : "=l"(d) : "l"(a), "l"(b), "l"(c))

__device__ __forceinline__ ull pack2(float lo, float hi) {
    ull r; asm("mov.b64 %0, {%1, %2};" : "=l"(r) : "f"(lo), "f"(hi)); return r;
}
__device__ __forceinline__ void unpack2(ull v, float& lo, float& hi) {
    asm("mov.b64 {%0, %1}, %2;" : "=f"(lo), "=f"(hi) : "l"(v));
}

// ---------------------------------------------------------------------------
// Prep: A = 1/s^2, B = -2*m/s^2 (transposed to [c][k]), t3[k] = sum_c m^2/s^2
// ---------------------------------------------------------------------------
__global__ __launch_bounds__(512)
void prep_kernel(const float* __restrict__ means,
                 const float* __restrict__ scales) {
    const int k = blockIdx.x;
    const int t = threadIdx.x;
    float s   = scales[k*CC + t];
    float m   = means [k*CC + t];
    float is2 = 1.0f / (s * s);
    g_At[t*KK + k] = is2;
    g_Bt[t*KK + k] = -2.0f * m * is2;
    float v = m * m * is2;
    #pragma unroll
    for (int o = 16; o > 0; o >>= 1)
        v += __shfl_down_sync(0xffffffffu, v, o);
    __shared__ float red[16];
    if ((t & 31) == 0) red[t >> 5] = v;
    __syncthreads();
    if (t < 16) {
        float x = red[t];
        #pragma unroll
        for (int o = 8; o > 0; o >>= 1)
            x += __shfl_down_sync(0xffffu, x, o);
        if (t == 0) g_t3[k] = x;
    }
}

// ---------------------------------------------------------------------------
// Phi: R4 geometry (128 rows x 64 k per block, 256 threads, 8n x 4k/thread),
// f32x2 FMAs, register-prefetch DOUBLE BUFFER (the single change vs R4).
//   dist[n,k] = -( sum_c f*(f*A[c,k] + B[c,k]) + t3[k] );  phi = exp(dist)(*w)
// ---------------------------------------------------------------------------
__global__ __launch_bounds__(256)
void phi_kernel(const float* __restrict__ f_i, const float* __restrict__ f_j,
                const float* __restrict__ weights) {
    const int isI = (blockIdx.y == 0);
    const float* __restrict__ f = isI ? f_i : f_j;
    float* __restrict__ phi = isI ? g_phi_i : g_phi_j;
    const int n0 = blockIdx.x * PHI_ROWS;

    __shared__ float fs[2][16][132];   // [buf][c_local][n_local]
    __shared__ float As[2][16][68];    // [buf][c_local][k] = 1/s^2
    __shared__ float Bs[2][16][68];    // [buf][c_local][k] = -2m/s^2

    const int t  = threadIdx.x;
    const int kg = t & 15;             // 16 k-groups of 4
    const int ng = t >> 4;             // 16 n-groups of 8
    const int kx = kg * 4;
    const int ny = ng * 8;

    // loader indices (fixed per thread)
    const int lrow0 = t >> 2;          // f: rows 0..63   (4 float4 per row)
    const int lrow1 = lrow0 + 64;      //    rows 64..127
    const int lc4   = (t & 3) * 4;
    const int lc    = t >> 4;          // A/B: 16 c, 16 float4 per c
    const int lk4   = (t & 15) * 4;

    ull acc[8][2];                     // [n][kp], each packs (k, k+1)
    #pragma unroll
    for (int i = 0; i < 8; i++) { acc[i][0] = 0ull; acc[i][1] = 0ull; }

    float4 xf0, xf1, xa, xb;
    // prologue: load chunk 0
    xf0 = *(const float4*)(f + (size_t)(n0 + lrow0) * CC + lc4);
    xf1 = *(const float4*)(f + (size_t)(n0 + lrow1) * CC + lc4);
    xa  = *(const float4*)(g_At + (size_t)lc * KK + lk4);
    xb  = *(const float4*)(g_Bt + (size_t)lc * KK + lk4);
    fs[0][lc4+0][lrow0] = xf0.x; fs[0][lc4+1][lrow0] = xf0.y;
    fs[0][lc4+2][lrow0] = xf0.z; fs[0][lc4+3][lrow0] = xf0.w;
    fs[0][lc4+0][lrow1] = xf1.x; fs[0][lc4+1][lrow1] = xf1.y;
    fs[0][lc4+2][lrow1] = xf1.z; fs[0][lc4+3][lrow1] = xf1.w;
    *(float4*)&As[0][lc][lk4] = xa;
    *(float4*)&Bs[0][lc][lk4] = xb;
    __syncthreads();

    #pragma unroll 1
    for (int it = 0; it < 32; it++) {
        const int buf = it & 1;
        const bool more = (it + 1 < 32);
        if (more) {
            int cc = (it + 1) * 16;
            xf0 = *(const float4*)(f + (size_t)(n0 + lrow0) * CC + cc + lc4);
            xf1 = *(const float4*)(f + (size_t)(n0 + lrow1) * CC + cc + lc4);
            xa  = *(const float4*)(g_At + (size_t)(cc + lc) * KK + lk4);
            xb  = *(const float4*)(g_Bt + (size_t)(cc + lc) * KK + lk4);
        }

        #pragma unroll
        for (int c = 0; c < 16; c++) {
            ulonglong2 ap = *(const ulonglong2*)&As[buf][c][kx];  // (a0,a1),(a2,a3)
            ulonglong2 bp = *(const ulonglong2*)&Bs[buf][c][kx];
            float4 fa = *(const float4*)&fs[buf][c][ny];
            float4 fb = *(const float4*)&fs[buf][c][ny + 4];
            float fv[8] = {fa.x, fa.y, fa.z, fa.w, fb.x, fb.y, fb.z, fb.w};
            #pragma unroll
            for (int n = 0; n < 8; n++) {
                ull fd = pack2(fv[n], fv[n]);
                ull t0, t1;
                FMA2(t0, fd, ap.x, bp.x);            // f*a + b
                FMA2(acc[n][0], fd, t0, acc[n][0]);  // += f*(f*a+b)
                FMA2(t1, fd, ap.y, bp.y);
                FMA2(acc[n][1], fd, t1, acc[n][1]);
            }
        }

        if (more) {
            const int nb = buf ^ 1;
            fs[nb][lc4+0][lrow0] = xf0.x; fs[nb][lc4+1][lrow0] = xf0.y;
            fs[nb][lc4+2][lrow0] = xf0.z; fs[nb][lc4+3][lrow0] = xf0.w;
            fs[nb][lc4+0][lrow1] = xf1.x; fs[nb][lc4+1][lrow1] = xf1.y;
            fs[nb][lc4+2][lrow1] = xf1.z; fs[nb][lc4+3][lrow1] = xf1.w;
            *(float4*)&As[nb][lc][lk4] = xa;
            *(float4*)&Bs[nb][lc][lk4] = xb;
        }
        __syncthreads();
    }

    // epilogue: d = -(acc + t3);  phi = exp(d) (* w for i-side)
    ull nt3[2];
    nt3[0] = pack2(-g_t3[kx],     -g_t3[kx + 1]);
    nt3[1] = pack2(-g_t3[kx + 2], -g_t3[kx + 3]);
    const ull m1 = pack2(-1.0f, -1.0f);

    float wv[4];
    #pragma unroll
    for (int j = 0; j < 4; j++)
        wv[j] = isI ? weights[kx + j] : 1.0f;

    int lnz = 0;
    #pragma unroll
    for (int n = 0; n < 8; n++) {
        float p[4];
        #pragma unroll
        for (int kp = 0; kp < 2; kp++) {
            ull d;
            FMA2(d, acc[n][kp], m1, nt3[kp]);  // -(acc) - t3
            float d0, d1; unpack2(d, d0, d1);
            p[2*kp]   = expf(d0) * wv[2*kp];
            p[2*kp+1] = expf(d1) * wv[2*kp+1];
            lnz |= (p[2*kp] != 0.0f) | (p[2*kp+1] != 0.0f);
        }
        *(float4*)(phi + (size_t)(n0 + ny + n) * KK + kx) =
            make_float4(p[0], p[1], p[2], p[3]);
    }
    int any = __syncthreads_or(lnz);
    if (t == 0) {
        g_nz[isI ? 0 : 1][2*blockIdx.x]     = any;
        g_nz[isI ? 0 : 1][2*blockIdx.x + 1] = any;
    }
}

// ---------------------------------------------------------------------------
// GEMM (R4-proven, unchanged): out[n,m] = sum_k phi_i[n,k]*phi_j[m,k].
// 64x64 tiles, 256 threads, 4x4 micro-tile. Zero tiles write zeros (exact).
// ---------------------------------------------------------------------------
__global__ __launch_bounds__(256)
void gemm_kernel(float* __restrict__ out) {
    const int bm = blockIdx.y;
    const int bn = blockIdx.x;
    const int t  = threadIdx.x;
    const int txm = (t & 15) * 4;
    const int tyn = (t >> 4) * 4;

    if (g_nz[0][bm] == 0 || g_nz[1][bn] == 0) {
        float4 z = make_float4(0.f, 0.f, 0.f, 0.f);
        #pragma unroll
        for (int i = 0; i < 4; i++) {
            size_t row = (size_t)(bm * 64 + tyn + i);
            *(float4*)(out + row * NN + bn * 64 + txm) = z;
        }
        return;
    }

    __shared__ float As[64][68];
    __shared__ float Bs[64][68];
    #pragma unroll
    for (int v = 0; v < 4; v++) {
        int vid = t + v * 256;
        int row = vid >> 4;
        int k4  = (vid & 15) * 4;
        float4 a = *(const float4*)(g_phi_i + (size_t)(bm * 64 + row) * KK + k4);
        As[k4+0][row] = a.x; As[k4+1][row] = a.y; As[k4+2][row] = a.z; As[k4+3][row] = a.w;
        float4 b = *(const float4*)(g_phi_j + (size_t)(bn * 64 + row) * KK + k4);
        Bs[k4+0][row] = b.x; Bs[k4+1][row] = b.y; Bs[k4+2][row] = b.z; Bs[k4+3][row] = b.w;
    }
    __syncthreads();

    float acc[4][4];
    #pragma unroll
    for (int i = 0; i < 4; i++)
        #pragma unroll
        for (int j = 0; j < 4; j++) acc[i][j] = 0.f;

    #pragma unroll 8
    for (int k = 0; k < 64; k++) {
        float4 a4 = *(const float4*)&As[k][tyn];
        float4 b4 = *(const float4*)&Bs[k][txm];
        float av[4] = {a4.x, a4.y, a4.z, a4.w};
        float bv[4] = {b4.x, b4.y, b4.z, b4.w};
        #pragma unroll
        for (int i = 0; i < 4; i++)
            #pragma unroll
            for (int j = 0; j < 4; j++)
                acc[i][j] = fmaf(av[i], bv[j], acc[i][j]);
    }

    #pragma unroll
    for (int i = 0; i < 4; i++) {
        size_t row = (size_t)(bm * 64 + tyn + i);
        *(float4*)(out + row * NN + bn * 64 + txm) =
            make_float4(acc[i][0], acc[i][1], acc[i][2], acc[i][3]);
    }
}

// ---------------------------------------------------------------------------
extern "C" void kernel_launch(void* const* d_in, const int* in_sizes, int n_in,
                              void* d_out, int out_size) {
    const float* f_i     = (const float*)d_in[0];
    const float* f_j     = (const float*)d_in[1];
    const float* means   = (const float*)d_in[2];
    const float* scales  = (const float*)d_in[3];
    const float* weights = (const float*)d_in[4];
    float* out = (float*)d_out;

    prep_kernel<<<KK, 512>>>(means, scales);
    phi_kernel<<<dim3(PHI_NBLK, 2), 256>>>(f_i, f_j, weights);
    gemm_kernel<<<dim3(NBLK, NBLK), 256>>>(out);
}